// round 5
// baseline (speedup 1.0000x reference)
#include <cuda_runtime.h>

#define SQH 0.70710678118654752440f
typedef unsigned long long u64;

// ---------------- f32x2 packed helpers -------------------------------------
__device__ __forceinline__ u64 pk(float v) {
    u64 r; asm("mov.b64 %0, {%1,%1};" : "=l"(r) : "f"(v)); return r;
}
__device__ __forceinline__ u64 pk2(float a, float b) {
    u64 r; asm("mov.b64 %0, {%1,%2};" : "=l"(r) : "f"(a), "f"(b)); return r;
}
__device__ __forceinline__ u64 f2fma(u64 a, u64 b, u64 c) {
    u64 d; asm("fma.rn.f32x2 %0, %1, %2, %3;" : "=l"(d) : "l"(a), "l"(b), "l"(c));
    return d;
}
__device__ __forceinline__ u64 f2add(u64 a, u64 b) {
    u64 d; asm("add.rn.f32x2 %0, %1, %2;" : "=l"(d) : "l"(a), "l"(b));
    return d;
}

// ---------------- warp-level gates: lane l holds amplitude index l ---------
template<int P>
__device__ __forceinline__ void w_rz(int l, float& ar, float& ai, float c, float s) {
    float t = ((l >> P) & 1) ? -s : s;
    float r = ar, i = ai;
    ar = fmaf(t, i, c * r);
    ai = fmaf(-t, r, c * i);
}
template<int PA, int PB>
__device__ __forceinline__ void w_zz(int l, float& ar, float& ai, float c, float s) {
    float t = (((l >> PA) ^ (l >> PB)) & 1) ? -s : s;
    float r = ar, i = ai;
    ar = fmaf(t, i, c * r);
    ai = fmaf(-t, r, c * i);
}
// M = (RX(-90)xRX(-90)) CNOT (RX(+90)xRX(+90)) : 3 independent shuffle pairs
template<int PA, int PB>
__device__ __forceinline__ void w_mid(int l, float& ar, float& ai) {
    float xbr = __shfl_xor_sync(0xffffffffu, ar, 1 << PB);
    float xbi = __shfl_xor_sync(0xffffffffu, ai, 1 << PB);
    float xar = __shfl_xor_sync(0xffffffffu, ar, 1 << PA);
    float xai = __shfl_xor_sync(0xffffffffu, ai, 1 << PA);
    float xdr = __shfl_xor_sync(0xffffffffu, ar, (1 << PA) | (1 << PB));
    float xdi = __shfl_xor_sync(0xffffffffu, ai, (1 << PA) | (1 << PB));
    float s1r = ar + xbr, s1i = ai + xbi;
    float t1r = xdr - xar, t1i = xdi - xai;
    float sg = ((l >> PA) & 1) ? -1.0f : 1.0f;
    ar = 0.5f * fmaf(-sg, t1i, s1r);
    ai = 0.5f * fmaf(sg, t1r, s1i);
}
template<int P>
__device__ __forceinline__ void w_ry(int l, float& ar, float& ai, float c, float sn) {
    float pr = __shfl_xor_sync(0xffffffffu, ar, 1 << P);
    float pi = __shfl_xor_sync(0xffffffffu, ai, 1 << P);
    float sg = ((l >> P) & 1) ? sn : -sn;
    ar = fmaf(sg, pr, c * ar);
    ai = fmaf(sg, pi, c * ai);
}
template<int PC, int PT>
__device__ __forceinline__ void w_cnot(int l, float& ar, float& ai) {
    float pr = __shfl_xor_sync(0xffffffffu, ar, 1 << PT);
    float pi = __shfl_xor_sync(0xffffffffu, ai, 1 << PT);
    if ((l >> PC) & 1) { ar = pr; ai = pi; }
}
template<int PC, int PT>
__device__ __forceinline__ void w_cry(int l, float& ar, float& ai, float c, float sn) {
    float pr = __shfl_xor_sync(0xffffffffu, ar, 1 << PT);
    float pi = __shfl_xor_sync(0xffffffffu, ai, 1 << PT);
    if ((l >> PC) & 1) {
        float sg = ((l >> PT) & 1) ? sn : -sn;
        ar = fmaf(sg, pr, c * ar);
        ai = fmaf(sg, pi, c * ai);
    }
}
template<int PC, int PT>
__device__ __forceinline__ void w_crx(int l, float& ar, float& ai, float c, float sn) {
    float pr = __shfl_xor_sync(0xffffffffu, ar, 1 << PT);
    float pi = __shfl_xor_sync(0xffffffffu, ai, 1 << PT);
    if ((l >> PC) & 1) {
        float r = ar, i = ai;
        ar = fmaf(sn, pi, c * r);
        ai = fmaf(-sn, pr, c * i);
    }
}

// Fused conv iteration: ZZ(t1) -> M -> RZ_b(t2)  (CZ pair cancels exactly)
template<int PA, int PB>
__device__ __forceinline__ void conv_f(int l, float& ar, float& ai, float t1, float t2) {
    float c1, s1, c2, s2;
    sincosf(0.5f * t1, &s1, &c1);
    sincosf(0.5f * t2, &s2, &c2);
    w_zz<PA, PB>(l, ar, ai, c1, s1);
    w_mid<PA, PB>(l, ar, ai);
    w_rz<PB>(l, ar, ai, c2, s2);
}

template<int PA, int PB>
__device__ __forceinline__ void pool_blk(int l, float& ar, float& ai, float w0, float w1) {
    float c0, s0, c1, s1;
    sincosf(0.5f * w0, &s0, &c0);
    sincosf(0.5f * w1, &s1, &c1);
    w_ry<PA>(l, ar, ai, c0, s0);
    w_ry<PB>(l, ar, ai, c1, s1);
    w_cnot<PA, PB>(l, ar, ai);
    w_cry<PB, PA>(l, ar, ai, c0, s0);
    w_crx<PA, PB>(l, ar, ai, c1, s1);
    w_cnot<PB, PA>(l, ar, ai);
}

// ---------------- mode transform: base-4 digit -> 3-basis coefficient ------
__device__ __forceinline__ void mode_xform(const float2* __restrict__ In,
                                           float2* __restrict__ Out, int S) {
    for (int idx = threadIdx.x; idx < 3 * S; idx += 1024) {
        int rest = idx / 3, e = idx - rest * 3;
        float2 a, b, o;
        if (e == 2) { a = In[S + rest]; b = In[2 * S + rest]; o = make_float2(0.5f * (a.x + b.x), 0.5f * (a.y + b.y)); }
        else if (e == 0) { a = In[rest]; b = In[3 * S + rest]; o = make_float2(0.5f * (a.x + b.x), 0.5f * (a.y + b.y)); }
        else { a = In[rest]; b = In[3 * S + rest]; o = make_float2(0.5f * (a.x - b.x), 0.5f * (a.y - b.y)); }
        Out[idx] = o;
    }
}

// ============== single fused kernel: per-block prep + batch eval ============
__global__ void __launch_bounds__(1024, 1)
qcnn_fused(const float* __restrict__ x, const float* __restrict__ conv,
           const float* __restrict__ pool, const float* __restrict__ fcw,
           const float* __restrict__ fcb, float2* __restrict__ out, int B2) {
    __shared__ float2 bufA[1088];        // U as bufA[j*33+l], later base-4 A
    __shared__ float2 bufB[768];
    __shared__ u64 sTB[544];             // broadcast T: class k at k*272, row r at r*10

    int tid = threadIdx.x;

    // ---- phase 1: simulate U, warp = column, lane = amplitude ----
    {
        int j = tid >> 5;
        int l = tid & 31;
        float ar = (l == j) ? 1.0f : 0.0f, ai = 0.0f;

        conv_f<4, 3>(l, ar, ai, conv[0], conv[2]);
        conv_f<3, 2>(l, ar, ai, conv[1], conv[3]);
        conv_f<2, 1>(l, ar, ai, conv[2], conv[4]);
        conv_f<1, 0>(l, ar, ai, conv[3], conv[5]);
        conv_f<0, 4>(l, ar, ai, conv[4], conv[6]);
        pool_blk<4, 3>(l, ar, ai, pool[0], pool[1]);
        conv_f<3, 2>(l, ar, ai, conv[15 + 0], conv[15 + 2]);
        conv_f<2, 1>(l, ar, ai, conv[15 + 1], conv[15 + 3]);
        conv_f<1, 0>(l, ar, ai, conv[15 + 2], conv[15 + 4]);
        conv_f<0, 3>(l, ar, ai, conv[15 + 3], conv[15 + 5]);
        pool_blk<3, 2>(l, ar, ai, pool[2], pool[3]);

        bufA[j * 33 + l] = make_float2(ar, ai);  // U[l][j]
    }
    __syncthreads();

    // ---- phase 2: A_c[s][t] folded with fc_w, scattered base-4 ----
    {
        int s = tid >> 5, t = tid & 31;
        float m2 = 0.0f, m3 = 0.0f;
#pragma unroll
        for (int k = 0; k < 32; k++) {
            float2 us = bufA[s * 33 + k];   // warp broadcast
            float2 ut = bufA[t * 33 + k];   // conflict-free (stride 33)
            float pr = us.x * ut.x + us.y * ut.y;
            m2 += ((k >> 2) & 1) ? -pr : pr;
            m3 += ((k >> 1) & 1) ? -pr : pr;
        }
        float a0 = fcw[0] * m2 + fcw[1] * m3;
        float a1 = fcw[2] * m2 + fcw[3] * m3;
        int d = 0;
#pragma unroll
        for (int P = 0; P < 5; P++)
            d += ((((s >> P) & 1) * 2 + ((t >> P) & 1)) << (2 * P));
        __syncthreads();
        bufA[d] = make_float2(a0, a1);
    }
    __syncthreads();

    // ---- phase 3: 5 mode transforms 1024 -> 243 ----
    mode_xform(bufA, bufB, 256); __syncthreads();
    mode_xform(bufB, bufA, 192); __syncthreads();
    mode_xform(bufA, bufB, 144); __syncthreads();
    mode_xform(bufB, bufA, 108); __syncthreads();
    mode_xform(bufA, bufB, 81);  __syncthreads();

    // ---- phase 4: broadcast-pack T into u64 {t,t}, row stride 10 ----
    if (tid < 486) {
        int cls = tid / 243, idx = tid - cls * 243;
        float v = cls ? bufB[idx].y : bufB[idx].x;
        sTB[cls * 272 + (idx / 9) * 10 + (idx % 9)] = pk(v);
    }
    __syncthreads();

    // ---- phase 5: evaluate 2 batch elements per thread (batch-packed) ----
    int b0 = blockIdx.x * 1024 + tid;
    if (b0 >= B2) return;

    float ca[5], sa[5], cb[5], sb[5];
#pragma unroll
    for (int q = 0; q < 5; q++) {
        __sincosf(__ldg(&x[b0 * 5 + q]), &sa[q], &ca[q]);
        __sincosf(__ldg(&x[(b0 + B2) * 5 + q]), &sb[q], &cb[q]);
    }
    u64 PC0 = pk2(ca[0], cb[0]), PS0 = pk2(sa[0], sb[0]);
    u64 PC1 = pk2(ca[1], cb[1]), PS1 = pk2(sa[1], sb[1]);
    u64 PC2 = pk2(ca[2], cb[2]), PS2 = pk2(sa[2], sb[2]);
    u64 PC3 = pk2(ca[3], cb[3]), PS3 = pk2(sa[3], sb[3]);
    u64 PC4 = pk2(ca[4], cb[4]), PS4 = pk2(sa[4], sb[4]);

    u64 accT[2];
#pragma unroll
    for (int e4 = 0; e4 < 3; e4++) {
        u64 acc3[2];
#pragma unroll
        for (int e3 = 0; e3 < 3; e3++) {
            u64 acc2[2];
#pragma unroll
            for (int e2 = 0; e2 < 3; e2++) {
                int r = (e4 * 3 + e3) * 3 + e2;
                u64 dcl[2];
#pragma unroll
                for (int k = 0; k < 2; k++) {
                    const u64* row = sTB + k * 272 + r * 10;
                    ulonglong2 q0 = *(const ulonglong2*)(row + 0);  // t0 t1
                    ulonglong2 q1 = *(const ulonglong2*)(row + 2);  // t2 t3
                    ulonglong2 q2 = *(const ulonglong2*)(row + 4);  // t4 t5
                    ulonglong2 q3 = *(const ulonglong2*)(row + 6);  // t6 t7
                    u64 t8 = row[8];
                    u64 g0 = f2fma(PS4, q1.x, f2fma(PC4, q0.y, q0.x));
                    u64 g1 = f2fma(PS4, q2.y, f2fma(PC4, q2.x, q1.y));
                    u64 g2 = f2fma(PS4, t8,   f2fma(PC4, q3.y, q3.x));
                    dcl[k] = f2fma(PS3, g2, f2fma(PC3, g1, g0));
                }
                if (e2 == 0)      { acc2[0] = dcl[0]; acc2[1] = dcl[1]; }
                else if (e2 == 1) { acc2[0] = f2fma(PC2, dcl[0], acc2[0]); acc2[1] = f2fma(PC2, dcl[1], acc2[1]); }
                else              { acc2[0] = f2fma(PS2, dcl[0], acc2[0]); acc2[1] = f2fma(PS2, dcl[1], acc2[1]); }
            }
            if (e3 == 0)      { acc3[0] = acc2[0]; acc3[1] = acc2[1]; }
            else if (e3 == 1) { acc3[0] = f2fma(PC1, acc2[0], acc3[0]); acc3[1] = f2fma(PC1, acc2[1], acc3[1]); }
            else              { acc3[0] = f2fma(PS1, acc2[0], acc3[0]); acc3[1] = f2fma(PS1, acc2[1], acc3[1]); }
        }
        if (e4 == 0)      { accT[0] = acc3[0]; accT[1] = acc3[1]; }
        else if (e4 == 1) { accT[0] = f2fma(PC0, acc3[0], accT[0]); accT[1] = f2fma(PC0, acc3[1], accT[1]); }
        else              { accT[0] = f2fma(PS0, acc3[0], accT[0]); accT[1] = f2fma(PS0, acc3[1], accT[1]); }
    }
    accT[0] = f2add(accT[0], pk(fcb[0]));  // class 0 for {b0, b0+B2}
    accT[1] = f2add(accT[1], pk(fcb[1]));  // class 1 for {b0, b0+B2}

    float o00, o01, o10, o11;
    asm("mov.b64 {%0,%1}, %2;" : "=f"(o00), "=f"(o01) : "l"(accT[0]));
    asm("mov.b64 {%0,%1}, %2;" : "=f"(o10), "=f"(o11) : "l"(accT[1]));
    out[b0]      = make_float2(o00, o10);
    out[b0 + B2] = make_float2(o01, o11);
}

extern "C" void kernel_launch(void* const* d_in, const int* in_sizes, int n_in,
                              void* d_out, int out_size) {
    const float* x    = (const float*)d_in[0];  // (B, 5)
    const float* conv = (const float*)d_in[1];  // (2, 15)
    const float* pool = (const float*)d_in[2];  // (2, 2)
    const float* fcw  = (const float*)d_in[3];  // (2, 2)
    const float* fcb  = (const float*)d_in[4];  // (2,)
    float2* out = (float2*)d_out;

    int B = in_sizes[0] / 5;
    int B2 = B / 2;
    int blocks = (B2 + 1023) / 1024;   // one 1024-thread block per 1024 pairs
    qcnn_fused<<<blocks, 1024>>>(x, conv, pool, fcw, fcb, out, B2);
}

// round 6
// speedup vs baseline: 1.3885x; 1.3885x over previous
#include <cuda_runtime.h>

#define SQH 0.70710678118654752440f
typedef unsigned long long u64;

// ---------------- f32x2 packed helpers -------------------------------------
__device__ __forceinline__ u64 pk(float v) {
    u64 r; asm("mov.b64 %0, {%1,%1};" : "=l"(r) : "f"(v)); return r;
}
__device__ __forceinline__ u64 pk2(float a, float b) {
    u64 r; asm("mov.b64 %0, {%1,%2};" : "=l"(r) : "f"(a), "f"(b)); return r;
}
__device__ __forceinline__ u64 f2fma(u64 a, u64 b, u64 c) {
    u64 d; asm("fma.rn.f32x2 %0, %1, %2, %3;" : "=l"(d) : "l"(a), "l"(b), "l"(c));
    return d;
}
__device__ __forceinline__ u64 f2add(u64 a, u64 b) {
    u64 d; asm("add.rn.f32x2 %0, %1, %2;" : "=l"(d) : "l"(a), "l"(b));
    return d;
}

// ---------------- warp-level gates: lane l holds amplitude index l ---------
template<int P>
__device__ __forceinline__ void w_rz(int l, float& ar, float& ai, float c, float s) {
    float t = ((l >> P) & 1) ? -s : s;
    float r = ar, i = ai;
    ar = fmaf(t, i, c * r);
    ai = fmaf(-t, r, c * i);
}
template<int PA, int PB>
__device__ __forceinline__ void w_zz(int l, float& ar, float& ai, float c, float s) {
    float t = (((l >> PA) ^ (l >> PB)) & 1) ? -s : s;
    float r = ar, i = ai;
    ar = fmaf(t, i, c * r);
    ai = fmaf(-t, r, c * i);
}
// M = (RX(-90)xRX(-90)) CNOT (RX(+90)xRX(+90)) : 3 independent shuffle pairs
template<int PA, int PB>
__device__ __forceinline__ void w_mid(int l, float& ar, float& ai) {
    float xbr = __shfl_xor_sync(0xffffffffu, ar, 1 << PB);
    float xbi = __shfl_xor_sync(0xffffffffu, ai, 1 << PB);
    float xar = __shfl_xor_sync(0xffffffffu, ar, 1 << PA);
    float xai = __shfl_xor_sync(0xffffffffu, ai, 1 << PA);
    float xdr = __shfl_xor_sync(0xffffffffu, ar, (1 << PA) | (1 << PB));
    float xdi = __shfl_xor_sync(0xffffffffu, ai, (1 << PA) | (1 << PB));
    float s1r = ar + xbr, s1i = ai + xbi;
    float t1r = xdr - xar, t1i = xdi - xai;
    float sg = ((l >> PA) & 1) ? -1.0f : 1.0f;
    ar = 0.5f * fmaf(-sg, t1i, s1r);
    ai = 0.5f * fmaf(sg, t1r, s1i);
}
template<int P>
__device__ __forceinline__ void w_ry(int l, float& ar, float& ai, float c, float sn) {
    float pr = __shfl_xor_sync(0xffffffffu, ar, 1 << P);
    float pi = __shfl_xor_sync(0xffffffffu, ai, 1 << P);
    float sg = ((l >> P) & 1) ? sn : -sn;
    ar = fmaf(sg, pr, c * ar);
    ai = fmaf(sg, pi, c * ai);
}
template<int PC, int PT>
__device__ __forceinline__ void w_cnot(int l, float& ar, float& ai) {
    float pr = __shfl_xor_sync(0xffffffffu, ar, 1 << PT);
    float pi = __shfl_xor_sync(0xffffffffu, ai, 1 << PT);
    if ((l >> PC) & 1) { ar = pr; ai = pi; }
}
template<int PC, int PT>
__device__ __forceinline__ void w_cry(int l, float& ar, float& ai, float c, float sn) {
    float pr = __shfl_xor_sync(0xffffffffu, ar, 1 << PT);
    float pi = __shfl_xor_sync(0xffffffffu, ai, 1 << PT);
    if ((l >> PC) & 1) {
        float sg = ((l >> PT) & 1) ? sn : -sn;
        ar = fmaf(sg, pr, c * ar);
        ai = fmaf(sg, pi, c * ai);
    }
}
template<int PC, int PT>
__device__ __forceinline__ void w_crx(int l, float& ar, float& ai, float c, float sn) {
    float pr = __shfl_xor_sync(0xffffffffu, ar, 1 << PT);
    float pi = __shfl_xor_sync(0xffffffffu, ai, 1 << PT);
    if ((l >> PC) & 1) {
        float r = ar, i = ai;
        ar = fmaf(sn, pi, c * r);
        ai = fmaf(-sn, pr, c * i);
    }
}

// Fused conv iteration: ZZ(t1) -> M -> RZ_b(t2)  (CZ pair cancels exactly)
template<int PA, int PB>
__device__ __forceinline__ void conv_f(int l, float& ar, float& ai,
                                       float2 a1, float2 a2) {
    w_zz<PA, PB>(l, ar, ai, a1.x, a1.y);
    w_mid<PA, PB>(l, ar, ai);
    w_rz<PB>(l, ar, ai, a2.x, a2.y);
}

template<int PA, int PB>
__device__ __forceinline__ void pool_blk(int l, float& ar, float& ai,
                                         float2 a0, float2 a1) {
    float c0 = a0.x, s0 = a0.y, c1 = a1.x, s1 = a1.y;
    w_ry<PA>(l, ar, ai, c0, s0);
    w_ry<PB>(l, ar, ai, c1, s1);
    w_cnot<PA, PB>(l, ar, ai);
    w_cry<PB, PA>(l, ar, ai, c0, s0);
    w_crx<PA, PB>(l, ar, ai, c1, s1);
    w_cnot<PB, PA>(l, ar, ai);
}

// ---------------- mode transform: base-4 digit -> 3-basis coefficient ------
__device__ __forceinline__ void mode_xform(const float2* __restrict__ In,
                                           float2* __restrict__ Out, int S) {
    for (int idx = threadIdx.x; idx < 3 * S; idx += 512) {
        int rest = idx / 3, e = idx - rest * 3;
        float2 a, b, o;
        if (e == 2) { a = In[S + rest]; b = In[2 * S + rest]; o = make_float2(0.5f * (a.x + b.x), 0.5f * (a.y + b.y)); }
        else if (e == 0) { a = In[rest]; b = In[3 * S + rest]; o = make_float2(0.5f * (a.x + b.x), 0.5f * (a.y + b.y)); }
        else { a = In[rest]; b = In[3 * S + rest]; o = make_float2(0.5f * (a.x - b.x), 0.5f * (a.y - b.y)); }
        Out[idx] = o;
    }
}

// ============== single fused kernel: per-block prep + batch eval ============
// 512 threads/block, 4 batch elements/thread, grid covers B in one wave.
__global__ void __launch_bounds__(512, 1)
qcnn_fused(const float* __restrict__ x, const float* __restrict__ conv,
           const float* __restrict__ pool, const float* __restrict__ fcw,
           const float* __restrict__ fcb, float2* __restrict__ out, int B4) {
    __shared__ float2 bufA[1088];   // U as bufA[j*33+l]; later base-4 A [1024]
    __shared__ float2 bufB[768];
    __shared__ u64 sT[272];         // class-packed T: row r at r*10, 9 used
    __shared__ float2 sAng[17];     // precomputed sincos(0.5*angle)

    int tid = threadIdx.x;

    // ---- phase 0: 17 angle sincos, once per block ----
    if (tid < 17) {
        float a;
        if (tid < 7)       a = conv[tid];           // layer0 conv[0..6]
        else if (tid < 13) a = conv[15 + tid - 7];  // layer1 conv[15..20]
        else               a = pool[tid - 13];      // pool[0..3]
        float cc, ss;
        sincosf(0.5f * a, &ss, &cc);
        sAng[tid] = make_float2(cc, ss);
    }
    __syncthreads();

    // ---- phase 1: simulate U; 16 warps x 2 columns, lane = amplitude ----
    {
        int w = tid >> 5;
        int l = tid & 31;
#pragma unroll
        for (int half = 0; half < 2; half++) {
            int j = w + half * 16;
            float ar = (l == j) ? 1.0f : 0.0f, ai = 0.0f;
            // Layer 0: wires [0..4], pos(w) = 4 - w
            conv_f<4, 3>(l, ar, ai, sAng[0], sAng[2]);
            conv_f<3, 2>(l, ar, ai, sAng[1], sAng[3]);
            conv_f<2, 1>(l, ar, ai, sAng[2], sAng[4]);
            conv_f<1, 0>(l, ar, ai, sAng[3], sAng[5]);
            conv_f<0, 4>(l, ar, ai, sAng[4], sAng[6]);
            pool_blk<4, 3>(l, ar, ai, sAng[13], sAng[14]);
            // Layer 1: wires [1..4]
            conv_f<3, 2>(l, ar, ai, sAng[7], sAng[9]);
            conv_f<2, 1>(l, ar, ai, sAng[8], sAng[10]);
            conv_f<1, 0>(l, ar, ai, sAng[9], sAng[11]);
            conv_f<0, 3>(l, ar, ai, sAng[10], sAng[12]);
            pool_blk<3, 2>(l, ar, ai, sAng[15], sAng[16]);
            bufA[j * 33 + l] = make_float2(ar, ai);   // U[l][j]
        }
    }
    __syncthreads();

    // ---- phase 2: A_c[s][t] folded with fc_w, scatter base-4 (2 per thread)
    {
        float r0[2], r1[2];
        int dd[2];
#pragma unroll
        for (int it = 0; it < 2; it++) {
            int idx = tid + it * 512;
            int s = idx >> 5, t = idx & 31;
            float m2 = 0.0f, m3 = 0.0f;
#pragma unroll
            for (int k = 0; k < 32; k++) {
                float2 us = bufA[s * 33 + k];
                float2 ut = bufA[t * 33 + k];
                float pr = us.x * ut.x + us.y * ut.y;
                m2 += ((k >> 2) & 1) ? -pr : pr;   // measured wire 2 (bit 2)
                m3 += ((k >> 1) & 1) ? -pr : pr;   // measured wire 3 (bit 1)
            }
            r0[it] = fcw[0] * m2 + fcw[1] * m3;
            r1[it] = fcw[2] * m2 + fcw[3] * m3;
            int d = 0;
#pragma unroll
            for (int P = 0; P < 5; P++)
                d += ((((s >> P) & 1) * 2 + ((t >> P) & 1)) << (2 * P));
            dd[it] = d;
        }
        __syncthreads();
        bufA[dd[0]] = make_float2(r0[0], r1[0]);
        bufA[dd[1]] = make_float2(r0[1], r1[1]);
    }
    __syncthreads();

    // ---- phase 3: 5 mode transforms 1024 -> 243 ----
    mode_xform(bufA, bufB, 256); __syncthreads();
    mode_xform(bufB, bufA, 192); __syncthreads();
    mode_xform(bufA, bufB, 144); __syncthreads();
    mode_xform(bufB, bufA, 108); __syncthreads();
    mode_xform(bufA, bufB, 81);  __syncthreads();

    // ---- phase 4: class-packed T rows, stride 10 u64, 16B aligned ----
    if (tid < 243) {
        float2 v = bufB[tid];
        sT[(tid / 9) * 10 + (tid % 9)] = pk2(v.x, v.y);
    }
    __syncthreads();

    // ---- phase 5: evaluate 4 batch elements per thread (class-packed) ----
    int b0 = blockIdx.x * 512 + tid;
    if (b0 >= B4) return;

    // trig weights; hoisted broadcast u64 for inner levels (q4,q3) + level q2
    u64 C4[4], S4[4], C3[4], S3[4], C2[4], S2[4];
    float c1f[4], s1f[4], c0f[4], s0f[4];
#pragma unroll
    for (int e = 0; e < 4; e++) {
        const float* xe = x + (b0 + e * B4) * 5;
        float cv, sv;
        __sincosf(__ldg(xe + 4), &sv, &cv); C4[e] = pk(cv); S4[e] = pk(sv);
        __sincosf(__ldg(xe + 3), &sv, &cv); C3[e] = pk(cv); S3[e] = pk(sv);
        __sincosf(__ldg(xe + 2), &sv, &cv); C2[e] = pk(cv); S2[e] = pk(sv);
        __sincosf(__ldg(xe + 1), &sv, &cv); c1f[e] = cv; s1f[e] = sv;
        __sincosf(__ldg(xe + 0), &sv, &cv); c0f[e] = cv; s0f[e] = sv;
    }

    u64 accT[4], acc3[4], acc2[4];
#pragma unroll
    for (int e4 = 0; e4 < 3; e4++) {
#pragma unroll
        for (int e3 = 0; e3 < 3; e3++) {
#pragma unroll
            for (int e2 = 0; e2 < 3; e2++) {
                int r = (e4 * 3 + e3) * 3 + e2;
                const u64* row = sT + r * 10;
                ulonglong2 q0 = *(const ulonglong2*)(row + 0);  // t0 t1
                ulonglong2 q1 = *(const ulonglong2*)(row + 2);  // t2 t3
                ulonglong2 q2 = *(const ulonglong2*)(row + 4);  // t4 t5
                ulonglong2 q3 = *(const ulonglong2*)(row + 6);  // t6 t7
                u64 t8 = row[8];
#pragma unroll
                for (int e = 0; e < 4; e++) {
                    u64 g0 = f2fma(S4[e], q1.x, f2fma(C4[e], q0.y, q0.x));
                    u64 g1 = f2fma(S4[e], q2.y, f2fma(C4[e], q2.x, q1.y));
                    u64 g2 = f2fma(S4[e], t8,   f2fma(C4[e], q3.y, q3.x));
                    u64 d  = f2fma(S3[e], g2,   f2fma(C3[e], g1, g0));
                    if (e2 == 0)      acc2[e] = d;
                    else if (e2 == 1) acc2[e] = f2fma(C2[e], d, acc2[e]);
                    else              acc2[e] = f2fma(S2[e], d, acc2[e]);
                }
            }
#pragma unroll
            for (int e = 0; e < 4; e++) {
                if (e3 == 0)      acc3[e] = acc2[e];
                else if (e3 == 1) acc3[e] = f2fma(pk(c1f[e]), acc2[e], acc3[e]);
                else              acc3[e] = f2fma(pk(s1f[e]), acc2[e], acc3[e]);
            }
        }
#pragma unroll
        for (int e = 0; e < 4; e++) {
            if (e4 == 0)      accT[e] = acc3[e];
            else if (e4 == 1) accT[e] = f2fma(pk(c0f[e]), acc3[e], accT[e]);
            else              accT[e] = f2fma(pk(s0f[e]), acc3[e], accT[e]);
        }
    }

    u64 bias = pk2(fcb[0], fcb[1]);   // {class0, class1}
    u64* o = (u64*)out;
#pragma unroll
    for (int e = 0; e < 4; e++)
        o[b0 + e * B4] = f2add(accT[e], bias);
}

extern "C" void kernel_launch(void* const* d_in, const int* in_sizes, int n_in,
                              void* d_out, int out_size) {
    const float* x    = (const float*)d_in[0];  // (B, 5)
    const float* conv = (const float*)d_in[1];  // (2, 15)
    const float* pool = (const float*)d_in[2];  // (2, 2)
    const float* fcw  = (const float*)d_in[3];  // (2, 2)
    const float* fcb  = (const float*)d_in[4];  // (2,)
    float2* out = (float2*)d_out;

    int B = in_sizes[0] / 5;
    int B4 = B / 4;                       // 4 elements per thread
    int blocks = (B4 + 511) / 512;        // 128 blocks @ B=262144 (one wave)
    qcnn_fused<<<blocks, 512>>>(x, conv, pool, fcw, fcb, out, B4);
}